// round 11
// baseline (speedup 1.0000x reference)
#include <cuda_runtime.h>
#include <cuda_bf16.h>
#include <cstdint>

#define NSTATES 512
#define MSYM    4096
#define BATCH   64
#define TMAXX   512
#define JQ      128        // states per CTA (4-way j split)

// dyn smem layout (bytes)
#define PLANE_OFF 0        // 2 bufs x [2 g][512] bf16 = 4096
#define XS_OFF    4096     // [2 g][512] int = 4096
#define REDS_OFF  8192     // [2][8] f32 (final-sum capture)
#define LAM_OFF   8320     // lambda[2 buf][2 g][4 r][16 w] f32 = 1024 B
#define MBAR_OFF  9344     // 8 B
#define P_OFF     9472     // 128 KB P quarter (128B aligned)
#define SMEM_TOT  (P_OFF + 64 * 128 * 16)   // 140544

__device__ float          g_em_lse[NSTATES];
__device__ float          g_EET[MSYM * NSTATES];      // exp(log_em)^T [m][j]
__device__ __nv_bfloat16  g_P[NSTATES * NSTATES];     // per-CTA per-thread swizzled blocks
__device__ float          g_prip[NSTATES];

__device__ __forceinline__ float warpSum(float v) {
#pragma unroll
    for (int o = 16; o; o >>= 1) v += __shfl_xor_sync(~0u, v, o);
    return v;
}
__device__ __forceinline__ unsigned s2u(const void* p) {
    return (unsigned)__cvta_generic_to_shared(p);
}
__device__ __forceinline__ unsigned crank() {
    unsigned r; asm("mov.u32 %0, %%cluster_ctarank;" : "=r"(r)); return r;
}
__device__ __forceinline__ unsigned mapa_u32(unsigned a, unsigned rk) {
    unsigned r; asm("mapa.shared::cluster.u32 %0, %1, %2;" : "=r"(r) : "r"(a), "r"(rk));
    return r;
}
__device__ __forceinline__ __nv_bfloat162 b2(unsigned u) {
    return *reinterpret_cast<__nv_bfloat162*>(&u);
}
__device__ __forceinline__ void mbar_wait_cl(unsigned a, unsigned ph) {
    asm volatile(
        "{\n\t.reg .pred P;\n"
        "W_%=:\n\t"
        "mbarrier.try_wait.parity.acquire.cluster.shared::cta.b64 P, [%0], %1, 0x989680;\n\t"
        "@!P bra W_%=;\n\t}"
        :: "r"(a), "r"(ph) : "memory");
}
__device__ __forceinline__ void arrive_own(unsigned a) {
    asm volatile("mbarrier.arrive.shared.b64 _, [%0];" :: "r"(a) : "memory");
}
__device__ __forceinline__ void arrive_rem(unsigned a) {
    asm volatile("mbarrier.arrive.release.cluster.shared::cluster.b64 _, [%0];" :: "r"(a) : "memory");
}
__device__ __forceinline__ void st_rem_u16(unsigned a, unsigned short v) {
    asm volatile("st.shared::cluster.u16 [%0], %1;" :: "r"(a), "h"(v) : "memory");
}
__device__ __forceinline__ void st_rem_f32(unsigned a, float v) {
    asm volatile("st.shared::cluster.f32 [%0], %1;" :: "r"(a), "f"(v) : "memory");
}

// ---------------- preproc ----------------
__global__ void k_em_lse_prior(const float* __restrict__ E, const float* __restrict__ pri) {
    if (blockIdx.x == NSTATES) {
        __shared__ float red[8];
        const int t = threadIdx.x;
        float e0 = __expf(pri[t]), e1 = __expf(pri[t + 256]);
        float s = warpSum(e0 + e1);
        if ((t & 31) == 0) red[t >> 5] = s;
        __syncthreads();
        float tot = 0.f;
#pragma unroll
        for (int w = 0; w < 8; w++) tot += red[w];
        float inv = 1.0f / tot;
        g_prip[t] = e0 * inv;  g_prip[t + 256] = e1 * inv;
        return;
    }
    const int j = blockIdx.x;
    const float4* row = reinterpret_cast<const float4*>(E + (size_t)j * MSYM);
    float s = 0.f;
    for (int i = threadIdx.x; i < MSYM / 4; i += blockDim.x) {
        float4 v = row[i];
        s += __expf(v.x) + __expf(v.y) + __expf(v.z) + __expf(v.w);
    }
    __shared__ float red[8];
    s = warpSum(s);
    if ((threadIdx.x & 31) == 0) red[threadIdx.x >> 5] = s;
    __syncthreads();
    if (threadIdx.x == 0) {
        float t = 0.f;
#pragma unroll
        for (int w = 0; w < 8; w++) t += red[w];
        g_em_lse[j] = __logf(t);
    }
}

__global__ void k_build_EET(const float* __restrict__ E) {
    __shared__ float tile[32][33];
    const int m0 = blockIdx.x * 32, j0 = blockIdx.y * 32;
#pragma unroll
    for (int i = 0; i < 32; i += 8)
        tile[threadIdx.y + i][threadIdx.x] =
            E[(size_t)(j0 + threadIdx.y + i) * MSYM + (m0 + threadIdx.x)];
    __syncthreads();
    const float lse = g_em_lse[j0 + threadIdx.x];
#pragma unroll
    for (int i = 0; i < 32; i += 8)
        g_EET[(size_t)(m0 + threadIdx.y + i) * NSTATES + (j0 + threadIdx.x)] =
            __expf(tile[threadIdx.x][threadIdx.y + i] - lse);
}

// P packed per (rank, compute-thread): thread tc = jl*4 + kq owns 128 bf16
// (its k-quarter for its jl), octet o stored at (o ^ (tc&15)) for LDS bank spread.
__global__ void k_build_P(const float* __restrict__ Tr) {
    const int k = blockIdx.x;
    float s = 0.f;
    for (int j = threadIdx.x; j < NSTATES; j += blockDim.x)
        s += __expf(Tr[(size_t)j * NSTATES + k]);
    __shared__ float red[8]; __shared__ float tot;
    s = warpSum(s);
    if ((threadIdx.x & 31) == 0) red[threadIdx.x >> 5] = s;
    __syncthreads();
    if (threadIdx.x == 0) {
        float t = 0.f;
#pragma unroll
        for (int w = 0; w < 8; w++) t += red[w];
        tot = 1.0f / t;
    }
    __syncthreads();
    const float inv = tot;
    const int kq = k >> 7, o = (k >> 3) & 15, e = k & 7;
    for (int j = threadIdx.x; j < NSTATES; j += blockDim.x) {
        float p = __expf(Tr[(size_t)j * NSTATES + k]) * inv;
        const int r = j >> 7, jl = j & 127;
        const int tc = jl * 4 + kq;
        g_P[(size_t)r * 65536 + tc * 128 + ((o ^ (tc & 15)) << 3) + e] = __float2bfloat16(p);
    }
}

// ---------------- forward: 4-CTA cluster, 2 batches per cluster ----------------
__global__ void __launch_bounds__(512, 1) __cluster_dims__(4, 1, 1)
k_forward(const int* __restrict__ x, const int* __restrict__ T, float* __restrict__ out) {
    extern __shared__ char sm[];
    __nv_bfloat16* plane = (__nv_bfloat16*)(sm + PLANE_OFF);   // [2 buf][2 g][512]
    int*   xs   = (int*)(sm + XS_OFF);
    float* redS = (float*)(sm + REDS_OFF);
    float* lam  = (float*)(sm + LAM_OFF);     // [buf][g][rank][16w]
    char*  Ps   = sm + P_OFF;

    const int tid  = threadIdx.x;
    const int kq   = tid & 3;            // k-quarter (lane-adjacent)
    const int jl   = tid >> 2;           // local state
    const int g    = tid & 1;            // this lane's batch
    const int lane = tid & 31;
    const unsigned rank = crank();
    const int jg   = (int)rank * JQ + jl;
    const int b0   = (blockIdx.x >> 2) * 2;

    const int Tb0 = T[b0], Tb1 = T[b0 + 1];
    const int maxTb = Tb0 > Tb1 ? Tb0 : Tb1;

    const unsigned base = s2u(sm);
    const unsigned own_mbar = base + MBAR_OFF;
    unsigned pb0 = mapa_u32(base, (rank + 1) & 3);
    unsigned pb1 = mapa_u32(base, (rank + 2) & 3);
    unsigned pb2 = mapa_u32(base, (rank + 3) & 3);

    if (tid == 0)
        asm volatile("mbarrier.init.shared.b64 [%0], 4;" :: "r"(own_mbar) : "memory");
    if (tid < 256) lam[tid] = 0.0f;      // zero lambda ring (before cluster sync)
    asm volatile("barrier.cluster.arrive.aligned;" ::: "memory");
    asm volatile("barrier.cluster.wait.aligned;"   ::: "memory");

    // ---- stage x rows into smem ----
    for (int i = tid; i < 2 * TMAXX; i += 512)
        xs[i] = x[(b0 + (i >> 9)) * TMAXX + (i & 511)];
    __syncthreads();

    // ---- init: w0 = eo0 * prior -> plane buf 1 (local + 3 peers) + lam ----
    if (tid < 256) {
        const int gi = tid >> 7, ji = tid & 127;
        const int jgi = (int)rank * JQ + ji;
        float v0 = g_EET[(size_t)xs[gi * TMAXX] * NSTATES + jgi] * g_prip[jgi];
        unsigned short vb = __bfloat16_as_ushort(__float2bfloat16(v0));
        const unsigned off = PLANE_OFF + (unsigned)(1024 + gi * 512 + jgi) * 2;
        plane[1024 + gi * 512 + jgi] = __ushort_as_bfloat16(vb);
        st_rem_u16(pb0 + off, vb); st_rem_u16(pb1 + off, vb); st_rem_u16(pb2 + off, vb);
        // per-warp max via shuffles (init only)
        float wm = v0;
#pragma unroll
        for (int o = 16; o; o >>= 1) wm = fmaxf(wm, __shfl_xor_sync(~0u, wm, o));
        if (lane == 0) {
            const int w8 = (tid >> 5) & 7;
            const int li = ((1 * 2 + gi) * 4 + (int)rank) * 16 + w8;
            lam[li] = wm;
            const unsigned lo = LAM_OFF + (unsigned)li * 4;
            st_rem_f32(pb0 + lo, wm); st_rem_f32(pb1 + lo, wm); st_rem_f32(pb2 + lo, wm);
        }
    }
    // ---- load 128 KB P quarter into smem ----
    {
        const uint4* src = reinterpret_cast<const uint4*>(g_P) + (size_t)rank * 8192;
        uint4* dst = reinterpret_cast<uint4*>(Ps);
        for (int i = tid; i < 8192; i += 512) dst[i] = src[i];
    }
    __syncthreads();
    if (tid < 4) {
        if (tid == 0) arrive_own(own_mbar);
        else {
            unsigned pb = (tid == 1) ? pb0 : (tid == 2) ? pb1 : pb2;
            arrive_rem(pb + MBAR_OFF);
        }
    }

    unsigned ph = 0;
    float s = 0.0f;
    const int TbG = g ? Tb1 : Tb0;               // this lane's batch length
    const int TbW = (tid >> 8) ? Tb1 : Tb0;      // redS-capture batch (plane view)
    const char* Pt = Ps + tid * 256;
    const int xsw = tid & 15;

    for (int t = 1; ; ++t) {
        // prefetch emission BEFORE the wait (independent of plane)
        {
            const int ti = (t < TMAXX) ? t : 0;
            // issued here; consumed at epilogue
        }
        const int ti = (t < TMAXX) ? t : 0;
        float eo = g_EET[(size_t)xs[g * TMAXX + ti] * NSTATES + jg];

        mbar_wait_cl(own_mbar, ph); ph ^= 1;     // plane[t&1] = w_{t-1} ready
        const int rb = t & 1, wb = rb ^ 1;

        // final-sum capture at t == Tb_g (rare)
        if (t == TbW) {
            const int gw = tid >> 8, wl = (tid >> 5) & 7;
            const unsigned* bufU = (const unsigned*)(sm + PLANE_OFF + rb * 2048);
            float2 f = __bfloat1622float2(b2(bufU[tid]));
            float ws = warpSum(f.x + f.y);
            if (lane == 0) redS[gw * 8 + wl] = ws;
        }

        // mu for this lane's g from 64 lambda scalars (hidden under compute)
        float invmu;
        {
            const int i16 = (tid >> 1) & 15;
            float4 l4 = *reinterpret_cast<const float4*>(lam + (rb * 2 + g) * 64 + i16 * 4);
            float m = fmaxf(fmaxf(l4.x, l4.y), fmaxf(l4.z, l4.w));
            m = fmaxf(m, __shfl_xor_sync(~0u, m, 2));
            m = fmaxf(m, __shfl_xor_sync(~0u, m, 4));
            m = fmaxf(m, __shfl_xor_sync(~0u, m, 8));
            m = fmaxf(m, __shfl_xor_sync(~0u, m, 16));
            if (t < TbG) s += __logf(m);
            invmu = __fdividef(1.0f, m);
        }
        if (t == maxTb) break;

        // compute: 16 octets x (1 P + 2 av + 8 HFMA2), both batches
        const char* a0b = sm + PLANE_OFF + rb * 2048 + kq * 256;
        const char* a1b = a0b + 1024;
        __nv_bfloat162 z = __float2bfloat162_rn(0.f);
        __nv_bfloat162 c00 = z, c01 = z, c02 = z, c03 = z;
        __nv_bfloat162 c10 = z, c11 = z, c12 = z, c13 = z;
#pragma unroll
        for (int o = 0; o < 16; o += 2) {
            uint4 p  = *reinterpret_cast<const uint4*>(Pt + (((o    ) ^ xsw) << 4));
            uint4 q  = *reinterpret_cast<const uint4*>(Pt + (((o + 1) ^ xsw) << 4));
            uint4 a0 = *reinterpret_cast<const uint4*>(a0b + o * 16);
            uint4 a1 = *reinterpret_cast<const uint4*>(a1b + o * 16);
            uint4 b0v = *reinterpret_cast<const uint4*>(a0b + o * 16 + 16);
            uint4 b1v = *reinterpret_cast<const uint4*>(a1b + o * 16 + 16);
            c00 = __hfma2(b2(p.x), b2(a0.x), c00);
            c01 = __hfma2(b2(p.y), b2(a0.y), c01);
            c02 = __hfma2(b2(p.z), b2(a0.z), c02);
            c03 = __hfma2(b2(p.w), b2(a0.w), c03);
            c10 = __hfma2(b2(p.x), b2(a1.x), c10);
            c11 = __hfma2(b2(p.y), b2(a1.y), c11);
            c12 = __hfma2(b2(p.z), b2(a1.z), c12);
            c13 = __hfma2(b2(p.w), b2(a1.w), c13);
            c00 = __hfma2(b2(q.x), b2(b0v.x), c00);
            c01 = __hfma2(b2(q.y), b2(b0v.y), c01);
            c02 = __hfma2(b2(q.z), b2(b0v.z), c02);
            c03 = __hfma2(b2(q.w), b2(b0v.w), c03);
            c10 = __hfma2(b2(q.x), b2(b1v.x), c10);
            c11 = __hfma2(b2(q.y), b2(b1v.y), c11);
            c12 = __hfma2(b2(q.z), b2(b1v.z), c12);
            c13 = __hfma2(b2(q.w), b2(b1v.w), c13);
        }
        float S0, S1;
        {
            float2 q0 = __bfloat1622float2(c00), q1 = __bfloat1622float2(c01);
            float2 q2 = __bfloat1622float2(c02), q3 = __bfloat1622float2(c03);
            S0 = ((q0.x + q0.y) + (q1.x + q1.y)) + ((q2.x + q2.y) + (q3.x + q3.y));
            q0 = __bfloat1622float2(c10); q1 = __bfloat1622float2(c11);
            q2 = __bfloat1622float2(c12); q3 = __bfloat1622float2(c13);
            S1 = ((q0.x + q0.y) + (q1.x + q1.y)) + ((q2.x + q2.y) + (q3.x + q3.y));
        }
        // butterfly over the 4 kq lanes: full dot products for this jl
        S0 += __shfl_xor_sync(~0u, S0, 1);
        S1 += __shfl_xor_sync(~0u, S1, 1);
        S0 += __shfl_xor_sync(~0u, S0, 2);
        S1 += __shfl_xor_sync(~0u, S1, 2);

        // this lane's batch value
        float v = (g ? S1 : S0) * eo * invmu;
        unsigned short vb = __bfloat16_as_ushort(__float2bfloat16(v));
        const unsigned off = PLANE_OFF + (unsigned)(wb * 1024 + g * 512 + jg) * 2;
        if (kq < 2) {
            plane[wb * 1024 + g * 512 + jg] = __ushort_as_bfloat16(vb);
            st_rem_u16(pb0 + off, vb);
        } else {
            st_rem_u16(pb1 + off, vb);
            st_rem_u16(pb2 + off, vb);
        }

        // warp-level lambda: max over the 8 jl of this warp (per g)
        float wm = v;
        wm = fmaxf(wm, __shfl_xor_sync(~0u, wm, 4));
        wm = fmaxf(wm, __shfl_xor_sync(~0u, wm, 8));
        wm = fmaxf(wm, __shfl_xor_sync(~0u, wm, 16));
        if (lane < 8) {
            const int dsel = (lane >> 1) & 3;
            const int li = ((wb * 2 + g) * 4 + (int)rank) * 16 + (tid >> 5);
            if (dsel == 0) lam[li] = wm;
            else {
                unsigned pb = (dsel == 1) ? pb0 : (dsel == 2) ? pb1 : pb2;
                st_rem_f32(pb + LAM_OFF + (unsigned)li * 4, wm);
            }
        }
        __syncthreads();
        if (tid < 4) {
            if (tid == 0) arrive_own(own_mbar);
            else {
                unsigned pb = (tid == 1) ? pb0 : (tid == 2) ? pb1 : pb2;
                arrive_rem(pb + MBAR_OFF);
            }
        }
    }

    __syncthreads();       // redS visible
    if (rank == 0 && tid < 2) {
        float tot = 0.f;
#pragma unroll
        for (int i = 0; i < 8; i++) tot += redS[tid * 8 + i];
        out[b0 + tid] = s + __logf(tot);
    }

    asm volatile("barrier.cluster.arrive.aligned;" ::: "memory");
    asm volatile("barrier.cluster.wait.aligned;"   ::: "memory");
}

// ---------------- launch ----------------
extern "C" void kernel_launch(void* const* d_in, const int* in_sizes, int n_in,
                              void* d_out, int out_size) {
    const int*   x   = (const int*)  d_in[0];
    const int*   T   = (const int*)  d_in[1];
    const float* E   = (const float*)d_in[2];
    const float* Tr  = (const float*)d_in[3];
    const float* pri = (const float*)d_in[4];
    float* out = (float*)d_out;

    cudaFuncSetAttribute(k_forward, cudaFuncAttributeMaxDynamicSharedMemorySize, SMEM_TOT);

    k_em_lse_prior<<<NSTATES + 1, 256>>>(E, pri);
    k_build_EET<<<dim3(MSYM / 32, NSTATES / 32), dim3(32, 8)>>>(E);
    k_build_P<<<NSTATES, 256>>>(Tr);
    k_forward<<<2 * BATCH, 512, SMEM_TOT>>>(x, T, out);
}

// round 12
// speedup vs baseline: 3.7878x; 3.7878x over previous
#include <cuda_runtime.h>
#include <cuda_bf16.h>
#include <cstdint>

#define NSTATES 512
#define MSYM    4096
#define BATCH   64
#define TMAXX   512
#define JQ      128        // states per CTA (4-way j split)

// dyn smem layout (bytes) — P no longer staged in smem (lives in registers)
#define PLANE_OFF 0        // 2 bufs x [2 g][512] bf16 = 4096
#define XS_OFF    4096     // [2 g][512] int = 4096
#define PART_OFF  8192     // [4 kq][2 g][128 jl] f32 = 4096
#define REDS_OFF  12288    // [2][8] f32 (final-sum capture)
#define LAM_OFF   12416    // lambda[2 buf][2 g][4 r][4 w] f32 = 256 B
#define MBAR_OFF  12672    // 8 B
#define SMEM_TOT  12800

__device__ float          g_em_lse[NSTATES];
__device__ float          g_EET[MSYM * NSTATES];      // exp(log_em)^T [m][j]
__device__ __nv_bfloat16  g_P[NSTATES * NSTATES];     // [(r*64+oct)*128+jl]*8+e
__device__ float          g_prip[NSTATES];

__device__ __forceinline__ float warpSum(float v) {
#pragma unroll
    for (int o = 16; o; o >>= 1) v += __shfl_xor_sync(~0u, v, o);
    return v;
}
// warp max of NONNEGATIVE float via u32 redux (bit pattern order-isomorphic)
__device__ __forceinline__ float warpMaxPos(float v) {
    unsigned d;
    asm("redux.sync.max.u32 %0, %1, 0xffffffff;" : "=r"(d) : "r"(__float_as_uint(v)));
    return __uint_as_float(d);
}
__device__ __forceinline__ unsigned s2u(const void* p) {
    return (unsigned)__cvta_generic_to_shared(p);
}
__device__ __forceinline__ unsigned crank() {
    unsigned r; asm("mov.u32 %0, %%cluster_ctarank;" : "=r"(r)); return r;
}
__device__ __forceinline__ unsigned mapa_u32(unsigned a, unsigned rk) {
    unsigned r; asm("mapa.shared::cluster.u32 %0, %1, %2;" : "=r"(r) : "r"(a), "r"(rk));
    return r;
}
__device__ __forceinline__ __nv_bfloat162 b2(unsigned u) {
    return *reinterpret_cast<__nv_bfloat162*>(&u);
}
__device__ __forceinline__ void mbar_wait_cl(unsigned a, unsigned ph) {
    asm volatile(
        "{\n\t.reg .pred P;\n"
        "W_%=:\n\t"
        "mbarrier.try_wait.parity.acquire.cluster.shared::cta.b64 P, [%0], %1, 0x989680;\n\t"
        "@!P bra W_%=;\n\t}"
        :: "r"(a), "r"(ph) : "memory");
}
__device__ __forceinline__ void arrive_own(unsigned a) {
    asm volatile("mbarrier.arrive.shared.b64 _, [%0];" :: "r"(a) : "memory");
}
__device__ __forceinline__ void arrive_rem(unsigned a) {
    asm volatile("mbarrier.arrive.release.cluster.shared::cluster.b64 _, [%0];" :: "r"(a) : "memory");
}
__device__ __forceinline__ void st_rem_u16(unsigned a, unsigned short v) {
    asm volatile("st.shared::cluster.u16 [%0], %1;" :: "r"(a), "h"(v) : "memory");
}
__device__ __forceinline__ void st_rem_f32(unsigned a, float v) {
    asm volatile("st.shared::cluster.f32 [%0], %1;" :: "r"(a), "f"(v) : "memory");
}

// ---------------- preproc ----------------
__global__ void k_em_lse_prior(const float* __restrict__ E, const float* __restrict__ pri) {
    if (blockIdx.x == NSTATES) {
        __shared__ float red[8];
        const int t = threadIdx.x;
        float e0 = __expf(pri[t]), e1 = __expf(pri[t + 256]);
        float s = warpSum(e0 + e1);
        if ((t & 31) == 0) red[t >> 5] = s;
        __syncthreads();
        float tot = 0.f;
#pragma unroll
        for (int w = 0; w < 8; w++) tot += red[w];
        float inv = 1.0f / tot;
        g_prip[t] = e0 * inv;  g_prip[t + 256] = e1 * inv;
        return;
    }
    const int j = blockIdx.x;
    const float4* row = reinterpret_cast<const float4*>(E + (size_t)j * MSYM);
    float s = 0.f;
    for (int i = threadIdx.x; i < MSYM / 4; i += blockDim.x) {
        float4 v = row[i];
        s += __expf(v.x) + __expf(v.y) + __expf(v.z) + __expf(v.w);
    }
    __shared__ float red[8];
    s = warpSum(s);
    if ((threadIdx.x & 31) == 0) red[threadIdx.x >> 5] = s;
    __syncthreads();
    if (threadIdx.x == 0) {
        float t = 0.f;
#pragma unroll
        for (int w = 0; w < 8; w++) t += red[w];
        g_em_lse[j] = __logf(t);
    }
}

__global__ void k_build_EET(const float* __restrict__ E) {
    __shared__ float tile[32][33];
    const int m0 = blockIdx.x * 32, j0 = blockIdx.y * 32;
#pragma unroll
    for (int i = 0; i < 32; i += 8)
        tile[threadIdx.y + i][threadIdx.x] =
            E[(size_t)(j0 + threadIdx.y + i) * MSYM + (m0 + threadIdx.x)];
    __syncthreads();
    const float lse = g_em_lse[j0 + threadIdx.x];
#pragma unroll
    for (int i = 0; i < 32; i += 8)
        g_EET[(size_t)(m0 + threadIdx.y + i) * NSTATES + (j0 + threadIdx.x)] =
            __expf(tile[threadIdx.x][threadIdx.y + i] - lse);
}

__global__ void k_build_P(const float* __restrict__ Tr) {
    const int k = blockIdx.x;
    float s = 0.f;
    for (int j = threadIdx.x; j < NSTATES; j += blockDim.x)
        s += __expf(Tr[(size_t)j * NSTATES + k]);
    __shared__ float red[8]; __shared__ float tot;
    s = warpSum(s);
    if ((threadIdx.x & 31) == 0) red[threadIdx.x >> 5] = s;
    __syncthreads();
    if (threadIdx.x == 0) {
        float t = 0.f;
#pragma unroll
        for (int w = 0; w < 8; w++) t += red[w];
        tot = 1.0f / t;
    }
    __syncthreads();
    const float inv = tot;
    for (int j = threadIdx.x; j < NSTATES; j += blockDim.x) {
        float p = __expf(Tr[(size_t)j * NSTATES + k]) * inv;
        const int r = j >> 7, jl = j & 127;
        g_P[(((size_t)r * 64 + (k >> 3)) * 128 + jl) * 8 + (k & 7)] = __float2bfloat16(p);
    }
}

// ---------------- forward: 4-CTA cluster, 2 batches per cluster ----------------
__global__ void __launch_bounds__(512, 1) __cluster_dims__(4, 1, 1)
k_forward(const int* __restrict__ x, const int* __restrict__ T, float* __restrict__ out) {
    extern __shared__ char sm[];
    __nv_bfloat16* plane = (__nv_bfloat16*)(sm + PLANE_OFF);   // [2 buf][2 g][512]
    int*   xs   = (int*)(sm + XS_OFF);
    float* part = (float*)(sm + PART_OFF);
    float* redS = (float*)(sm + REDS_OFF);
    float* lam  = (float*)(sm + LAM_OFF);     // [buf][g][r][w]

    const int tid  = threadIdx.x;
    const int kq   = tid >> 7;           // compute k-quarter (and owner g for tid<256)
    const int jl   = tid & 127;
    const int lane = tid & 31;
    const unsigned rank = crank();
    const int jg   = (int)rank * JQ + jl;
    const int b0   = (blockIdx.x >> 2) * 2;

    const int Tb0 = T[b0], Tb1 = T[b0 + 1];
    const int maxTb = Tb0 > Tb1 ? Tb0 : Tb1;

    const unsigned base = s2u(sm);
    const unsigned own_mbar = base + MBAR_OFF;
    unsigned pb0 = mapa_u32(base, (rank + 1) & 3);
    unsigned pb1 = mapa_u32(base, (rank + 2) & 3);
    unsigned pb2 = mapa_u32(base, (rank + 3) & 3);

    if (tid == 0)
        asm volatile("mbarrier.init.shared.b64 [%0], 4;" :: "r"(own_mbar) : "memory");
    asm volatile("barrier.cluster.arrive.aligned;" ::: "memory");
    asm volatile("barrier.cluster.wait.aligned;"   ::: "memory");

    // ---- stage x rows into smem ----
    for (int i = tid; i < 2 * TMAXX; i += 512)
        xs[i] = x[(b0 + (i >> 9)) * TMAXX + (i & 511)];
    __syncthreads();

    // ---- P slice into REGISTERS: 16 uint4 = 128 bf16, constant all steps ----
    uint4 preg[16];
    {
        const uint4* Pg = reinterpret_cast<const uint4*>(g_P);
        const size_t tb = ((size_t)rank * 64 + (size_t)kq * 16) * 128 + jl;
#pragma unroll
        for (int o = 0; o < 16; ++o) preg[o] = Pg[tb + (size_t)o * 128];
    }

    // ---- init: w0 = eo0 * prior -> plane buf 1 (local + 3 peers) + lam maxima ----
    if (tid < 256) {
        const int g = kq;  // 0 or 1
        const int w = (tid >> 5) & 3;
        float v0 = g_EET[(size_t)xs[g * TMAXX] * NSTATES + jg] * g_prip[jg];
        unsigned short vb = __bfloat16_as_ushort(__float2bfloat16(v0));
        const unsigned off = PLANE_OFF + (unsigned)(1024 + g * 512 + jg) * 2;
        plane[1024 + g * 512 + jg] = __ushort_as_bfloat16(vb);
        st_rem_u16(pb0 + off, vb); st_rem_u16(pb1 + off, vb); st_rem_u16(pb2 + off, vb);
        float wm = warpMaxPos(v0);
        if (lane == 0) {
            const int li = ((1 * 2 + g) * 4 + (int)rank) * 4 + w;
            lam[li] = wm;
            const unsigned lo = LAM_OFF + (unsigned)li * 4;
            st_rem_f32(pb0 + lo, wm); st_rem_f32(pb1 + lo, wm); st_rem_f32(pb2 + lo, wm);
        }
    }
    __syncthreads();
    if (tid < 4) {
        if (tid == 0) arrive_own(own_mbar);
        else {
            unsigned pb = (tid == 1) ? pb0 : (tid == 2) ? pb1 : pb2;
            arrive_rem(pb + MBAR_OFF);
        }
    }

    unsigned ph = 0;
    float s = 0.0f;
    const int TbG = (kq & 1) ? Tb1 : Tb0;        // owner's batch length (tid<256)
    const int TbW = (tid >> 8) ? Tb1 : Tb0;      // capture batch (tid<512 view)

    for (int t = 1; ; ++t) {
        // prefetch emission BEFORE the wait (independent of plane)
        float eo = 0.f;
        if (tid < 256) {
            const int ti = (t < TMAXX) ? t : 0;
            eo = g_EET[(size_t)xs[kq * TMAXX + ti] * NSTATES + jg];
        }

        mbar_wait_cl(own_mbar, ph); ph ^= 1;     // plane[t&1] = w_{t-1} ready
        const int rb = t & 1, wb = rb ^ 1;

        // final-sum capture at t == Tb_g (rare)
        if (t == TbW) {
            const int gw = tid >> 8, wl = (tid >> 5) & 7;
            const unsigned* bufU = (const unsigned*)(sm + PLANE_OFF + rb * 2048);
            float2 f = __bfloat1622float2(b2(bufU[tid]));
            float ws = warpSum(f.x + f.y);
            if (lane == 0) redS[gw * 8 + wl] = ws;
        }

        // owner: global max from 16 scalars (latency hidden under compute)
        float invmu = 0.f;
        if (tid < 256) {
            const int g = kq;
            const float* lp = lam + (rb * 2 + g) * 16;
            float4 l0 = *reinterpret_cast<const float4*>(lp);
            float4 l1 = *reinterpret_cast<const float4*>(lp + 4);
            float4 l2 = *reinterpret_cast<const float4*>(lp + 8);
            float4 l3 = *reinterpret_cast<const float4*>(lp + 12);
            float mu = fmaxf(fmaxf(fmaxf(fmaxf(l0.x, l0.y), fmaxf(l0.z, l0.w)),
                                   fmaxf(fmaxf(l1.x, l1.y), fmaxf(l1.z, l1.w))),
                             fmaxf(fmaxf(fmaxf(l2.x, l2.y), fmaxf(l2.z, l2.w)),
                                   fmaxf(fmaxf(l3.x, l3.y), fmaxf(l3.z, l3.w))));
            if (t < TbG) s += __logf(mu);
            invmu = __fdividef(1.0f, mu);
        }
        if (t == maxTb) break;

        // compute: 16 octets x (2 av LDS + 8 HFMA2), P from registers
        const char* a0b = sm + PLANE_OFF + rb * 2048 + kq * 256;
        const char* a1b = a0b + 1024;
        __nv_bfloat162 z = __float2bfloat162_rn(0.f);
        __nv_bfloat162 c00 = z, c01 = z, c02 = z, c03 = z;
        __nv_bfloat162 c10 = z, c11 = z, c12 = z, c13 = z;
#pragma unroll
        for (int o = 0; o < 16; ++o) {
            const uint4 p = preg[o];
            uint4 a0 = *reinterpret_cast<const uint4*>(a0b + o * 16);
            uint4 a1 = *reinterpret_cast<const uint4*>(a1b + o * 16);
            c00 = __hfma2(b2(p.x), b2(a0.x), c00);
            c01 = __hfma2(b2(p.y), b2(a0.y), c01);
            c02 = __hfma2(b2(p.z), b2(a0.z), c02);
            c03 = __hfma2(b2(p.w), b2(a0.w), c03);
            c10 = __hfma2(b2(p.x), b2(a1.x), c10);
            c11 = __hfma2(b2(p.y), b2(a1.y), c11);
            c12 = __hfma2(b2(p.z), b2(a1.z), c12);
            c13 = __hfma2(b2(p.w), b2(a1.w), c13);
        }
        {
            float2 q0 = __bfloat1622float2(c00), q1 = __bfloat1622float2(c01);
            float2 q2 = __bfloat1622float2(c02), q3 = __bfloat1622float2(c03);
            part[(kq * 2 + 0) * 128 + jl] = ((q0.x + q0.y) + (q1.x + q1.y)) + ((q2.x + q2.y) + (q3.x + q3.y));
            q0 = __bfloat1622float2(c10); q1 = __bfloat1622float2(c11);
            q2 = __bfloat1622float2(c12); q3 = __bfloat1622float2(c13);
            part[(kq * 2 + 1) * 128 + jl] = ((q0.x + q0.y) + (q1.x + q1.y)) + ((q2.x + q2.y) + (q3.x + q3.y));
        }
        __syncthreads();   // part[] visible; all plane[rb]/lam[rb] reads done

        if (tid < 256) {
            const int g = kq;
            const int w = (tid >> 5) & 3;
            float sum = part[(0 * 2 + g) * 128 + jl] + part[(1 * 2 + g) * 128 + jl]
                      + part[(2 * 2 + g) * 128 + jl] + part[(3 * 2 + g) * 128 + jl];
            float v = sum * eo * invmu;
            unsigned short vb = __bfloat16_as_ushort(__float2bfloat16(v));
            const unsigned off = PLANE_OFF + (unsigned)(wb * 1024 + g * 512 + jg) * 2;
            plane[wb * 1024 + g * 512 + jg] = __ushort_as_bfloat16(vb);
            st_rem_u16(pb0 + off, vb); st_rem_u16(pb1 + off, vb); st_rem_u16(pb2 + off, vb);
            float wm = warpMaxPos(v);
            if (lane == 0) {
                const int li = ((wb * 2 + g) * 4 + (int)rank) * 4 + w;
                lam[li] = wm;
                const unsigned lo = LAM_OFF + (unsigned)li * 4;
                st_rem_f32(pb0 + lo, wm); st_rem_f32(pb1 + lo, wm); st_rem_f32(pb2 + lo, wm);
            }
            asm volatile("bar.sync 1, 256;" ::: "memory");
            if (tid < 4) {
                if (tid == 0) arrive_own(own_mbar);
                else {
                    unsigned pb = (tid == 1) ? pb0 : (tid == 2) ? pb1 : pb2;
                    arrive_rem(pb + MBAR_OFF);
                }
            }
        }
    }

    __syncthreads();       // redS visible
    if (rank == 0 && (tid == 0 || tid == 128)) {
        const int g = tid >> 7;
        float tot = 0.f;
#pragma unroll
        for (int i = 0; i < 8; i++) tot += redS[g * 8 + i];
        out[b0 + g] = s + __logf(tot);
    }

    asm volatile("barrier.cluster.arrive.aligned;" ::: "memory");
    asm volatile("barrier.cluster.wait.aligned;"   ::: "memory");
}

// ---------------- launch ----------------
extern "C" void kernel_launch(void* const* d_in, const int* in_sizes, int n_in,
                              void* d_out, int out_size) {
    const int*   x   = (const int*)  d_in[0];
    const int*   T   = (const int*)  d_in[1];
    const float* E   = (const float*)d_in[2];
    const float* Tr  = (const float*)d_in[3];
    const float* pri = (const float*)d_in[4];
    float* out = (float*)d_out;

    cudaFuncSetAttribute(k_forward, cudaFuncAttributeMaxDynamicSharedMemorySize, SMEM_TOT);

    k_em_lse_prior<<<NSTATES + 1, 256>>>(E, pri);
    k_build_EET<<<dim3(MSYM / 32, NSTATES / 32), dim3(32, 8)>>>(E);
    k_build_P<<<NSTATES, 256>>>(Tr);
    k_forward<<<2 * BATCH, 512, SMEM_TOT>>>(x, T, out);
}